// round 2
// baseline (speedup 1.0000x reference)
#include <cuda_runtime.h>
#include <cstdint>
#include <math.h>

typedef unsigned long long u64;
typedef unsigned int u32;

#define K_PRE 6000
#define K_POST 300
#define NMS_TH 0.7f
#define NROW 6016
#define NWORD 94
#define WSTRIDE 96
#define MAXB 2
#define MAXN 262144
#define CAP 16384

__device__ u64    g_keys[MAXB * MAXN];
__device__ int    g_hist1[MAXB * 65536];
__device__ int    g_hist2[MAXB * 256];
__device__ int    g_t1[MAXB];
__device__ int    g_krem[MAXB];
__device__ u32    g_T24[MAXB];
__device__ int    g_ccount[MAXB];
__device__ u64    g_cand[MAXB * CAP];
__device__ u32    g_sidx[MAXB * K_PRE];
__device__ float4 g_box[2 * MAXB * NROW];
__device__ float  g_area[2 * MAXB * NROW];
__device__ u64    g_mask[(size_t)2 * MAXB * NROW * WSTRIDE];
__device__ u64    g_keep[2 * MAXB * NWORD];
__device__ int    g_prog[MAXB];
__device__ int    g_comb[MAXB];

__global__ void k_zero(int B) {
    int i = blockIdx.x * blockDim.x + threadIdx.x;
    int stride = gridDim.x * blockDim.x;
    for (int idx = i; idx < B * 65536; idx += stride) g_hist1[idx] = 0;
    if (i < B * 256) g_hist2[i] = 0;
    if (i < B) { g_ccount[i] = 0; g_prog[i] = 0; g_comb[i] = 0; }
}

__global__ void k_keys(const float* __restrict__ scores, int B, int N) {
    int idx = blockIdx.x * blockDim.x + threadIdx.x;
    if (idx >= B * N) return;
    int b = idx / N;
    int i = idx - b * N;
    u32 u = __float_as_uint(scores[(size_t)idx * 2 + 1]);
    u = (u & 0x80000000u) ? ~u : (u | 0x80000000u);
    u64 key = ((u64)u << 32) | (u32)(0xFFFFFFFFu - (u32)i);
    g_keys[idx] = key;
    atomicAdd(&g_hist1[b * 65536 + (int)(key >> 48)], 1);
}

__global__ void k_scan1(void) {
    int b = blockIdx.x;
    int t = threadIdx.x;                  // 256 threads
    __shared__ int part[256];
    const int* h = &g_hist1[b * 65536];
    int sum = 0;
    for (int k = 0; k < 256; k++) sum += h[t * 256 + k];
    part[t] = sum;
    __syncthreads();
    if (t == 0) {
        int cum = 0, seg = 255;
        for (; seg > 0; seg--) {
            if (cum + part[seg] >= K_PRE) break;
            cum += part[seg];
        }
        int bin = seg * 256 + 255;
        for (;; bin--) {
            int c = h[bin];
            if (cum + c >= K_PRE || bin == 0) break;
            cum += c;
        }
        g_t1[b] = bin;
        g_krem[b] = K_PRE - cum;
    }
}

__global__ void k_hist2(int B, int N) {
    int idx = blockIdx.x * blockDim.x + threadIdx.x;
    if (idx >= B * N) return;
    int b = idx / N;
    u64 key = g_keys[idx];
    if ((int)(key >> 48) == g_t1[b])
        atomicAdd(&g_hist2[b * 256 + (int)((key >> 40) & 255)], 1);
}

__global__ void k_scan2(void) {
    int b = blockIdx.x;
    if (threadIdx.x != 0) return;
    int krem = g_krem[b];
    int cum = 0, bin = 255;
    for (;; bin--) {
        int c = g_hist2[b * 256 + bin];
        if (cum + c >= krem || bin == 0) break;
        cum += c;
    }
    g_T24[b] = ((u32)g_t1[b] << 8) | (u32)bin;
}

__global__ void k_compact(int B, int N) {
    int idx = blockIdx.x * blockDim.x + threadIdx.x;
    if (idx >= B * N) return;
    int b = idx / N;
    u64 key = g_keys[idx];
    if ((u32)(key >> 40) >= g_T24[b]) {
        int p = atomicAdd(&g_ccount[b], 1);
        if (p < CAP) g_cand[b * CAP + p] = key;
    }
}

__global__ void k_rank(void) {
    int b = blockIdx.y;
    int C = g_ccount[b];
    if (C > CAP) C = CAP;
    if ((int)blockIdx.x * 128 >= C) return;   // uniform per block
    int j = blockIdx.x * 128 + threadIdx.x;
    __shared__ u64 tile[1024];
    u64 mykey = (j < C) ? g_cand[b * CAP + j] : 0ull;
    int rank = 0;
    for (int base = 0; base < C; base += 1024) {
        int nt = min(1024, C - base);
        for (int t = threadIdx.x; t < nt; t += 128) tile[t] = g_cand[b * CAP + base + t];
        __syncthreads();
        if (j < C)
            for (int t = 0; t < nt; t++) rank += (tile[t] > mykey) ? 1 : 0;
        __syncthreads();
    }
    if (j < C && rank < K_PRE)
        g_sidx[b * K_PRE + rank] = 0xFFFFFFFFu - (u32)(mykey & 0xFFFFFFFFull);
}

__global__ void k_gather(const float* __restrict__ deltas, const float* __restrict__ iminfo,
                         const float* __restrict__ anchors, int B, int N) {
    int idx = blockIdx.x * blockDim.x + threadIdx.x;
    if (idx >= B * NROW) return;
    int b = idx / NROW;
    int r = idx - b * NROW;
    float4 bl = make_float4(0.f, 0.f, 0.f, 0.f);
    float4 br = make_float4(0.f, 0.f, 0.f, 0.f);
    float al = 1.0f, ar = 1.0f;
    if (r < K_PRE) {
        int i = (int)g_sidx[b * K_PRE + r];
        const float* a = anchors + (size_t)i * 4;
        float w = a[2] - a[0] + 1.0f;
        float h = a[3] - a[1] + 1.0f;
        float cx = a[0] + 0.5f * w;
        float cy = a[1] + 0.5f * h;
        const float* d = deltas + ((size_t)b * N + i) * 6;
        float d0 = d[0], d1 = d[1], d2 = d[2], d3 = d[3], d4 = d[4], d5 = d[5];
        float Hm1 = iminfo[b * 3 + 0] - 1.0f;
        float Wm1 = iminfo[b * 3 + 1] - 1.0f;
        float eh = (float)exp((double)d3) * h;     // accurate exp (fast-math safe)
        {
            float pcx = d0 * w + cx, pcy = d1 * h + cy;
            float pw = (float)exp((double)d2) * w;
            float x1 = fminf(fmaxf(pcx - 0.5f * pw, 0.f), Wm1);
            float y1 = fminf(fmaxf(pcy - 0.5f * eh, 0.f), Hm1);
            float x2 = fminf(fmaxf(pcx + 0.5f * pw, 0.f), Wm1);
            float y2 = fminf(fmaxf(pcy + 0.5f * eh, 0.f), Hm1);
            bl = make_float4(x1, y1, x2, y2);
            al = (x2 - x1 + 1.0f) * (y2 - y1 + 1.0f);
        }
        {
            float pcx = d4 * w + cx, pcy = d1 * h + cy;
            float pw = (float)exp((double)d5) * w;
            float x1 = fminf(fmaxf(pcx - 0.5f * pw, 0.f), Wm1);
            float y1 = fminf(fmaxf(pcy - 0.5f * eh, 0.f), Hm1);
            float x2 = fminf(fmaxf(pcx + 0.5f * pw, 0.f), Wm1);
            float y2 = fminf(fmaxf(pcy + 0.5f * eh, 0.f), Hm1);
            br = make_float4(x1, y1, x2, y2);
            ar = (x2 - x1 + 1.0f) * (y2 - y1 + 1.0f);
        }
    }
    g_box[(b * 2 + 0) * NROW + r] = bl;
    g_box[(b * 2 + 1) * NROW + r] = br;
    g_area[(b * 2 + 0) * NROW + r] = al;
    g_area[(b * 2 + 1) * NROW + r] = ar;
}

__global__ void k_mask(void) {
    int bset = blockIdx.z;
    int cc = blockIdx.x;       // column word
    int rc = blockIdx.y;       // row chunk
    if (cc < rc) return;       // only j > i words are read
    __shared__ float sx1[64], sy1[64], sx2[64], sy2[64], sar[64];
    int t = threadIdx.x;
    int jg0 = cc * 64;
    {
        float4 bj = g_box[bset * NROW + jg0 + t];
        sx1[t] = bj.x; sy1[t] = bj.y; sx2[t] = bj.z; sy2[t] = bj.w;
        sar[t] = g_area[bset * NROW + jg0 + t];
    }
    __syncthreads();
    int i = rc * 64 + t;
    if (i >= K_PRE) return;
    float4 bi = g_box[bset * NROW + i];
    float ai = g_area[bset * NROW + i];
    u64 word = 0;
#pragma unroll 8
    for (int k = 0; k < 64; k++) {
        int jg = jg0 + k;
        float xx1 = fmaxf(bi.x, sx1[k]);
        float yy1 = fmaxf(bi.y, sy1[k]);
        float xx2 = fminf(bi.z, sx2[k]);
        float yy2 = fminf(bi.w, sy2[k]);
        float ow = xx2 - xx1 + 1.0f;
        float oh = yy2 - yy1 + 1.0f;
        bool sup = false;
        if (ow > 0.0f && oh > 0.0f && jg > i && jg < K_PRE) {
            float inter = ow * oh;
            float uni = ai + sar[k] - inter;
            sup = __fdiv_rn(inter, uni) > NMS_TH;
        }
        if (sup) word |= 1ull << k;
    }
    g_mask[((size_t)bset * NROW + i) * WSTRIDE + cc] = word;
}

__global__ void k_nms_scan(void) {
    int b = blockIdx.x;
    __shared__ u64 sh_keep[2][NWORD];
    __shared__ u64 sh_diag[2][64];
    __shared__ u64 sh_next[2];
    __shared__ u64 sh_cur[2];
    __shared__ int sh_comb, sh_done, sh_chunks;
    int t = threadIdx.x;          // 128
    int set = t >> 6;
    int lt = t & 63;
    const u64* M = &g_mask[(size_t)(b * 2 + set) * NROW * WSTRIDE];
    if (t == 0) { sh_comb = 0; sh_done = 0; sh_chunks = 0; sh_cur[0] = 0; sh_cur[1] = 0; }
    __syncthreads();
    for (int c = 0; c < NWORD; c++) {
        if (t < 2) sh_next[t] = 0;
        sh_diag[set][lt] = M[(size_t)(c * 64 + lt) * WSTRIDE + c];
        __syncthreads();
        if (lt == 0) {
            u64 cur = sh_cur[set];
            u64 keep = 0;
            int limit = min(64, K_PRE - c * 64);
            for (int k = 0; k < 64; k++) {
                if (k < limit && !((cur >> k) & 1ull)) {
                    keep |= 1ull << k;
                    cur |= sh_diag[set][k];
                }
            }
            sh_keep[set][c] = keep;
            g_keep[(b * 2 + set) * NWORD + c] = keep;
        }
        __syncthreads();
        if (t == 0) {
            sh_comb += __popcll(sh_keep[0][c] & sh_keep[1][c]);
            sh_chunks = c + 1;
            if (sh_comb >= K_POST) sh_done = 1;
        }
        __syncthreads();
        if (sh_done) break;
        if (c + 1 < NWORD) {
            u64 acc = 0;
            for (int r = lt; r < (c + 1) * 64; r += 64) {
                u64 kw = sh_keep[set][r >> 6];
                if ((kw >> (r & 63)) & 1ull) acc |= M[(size_t)r * WSTRIDE + (c + 1)];
            }
            for (int o = 16; o; o >>= 1) acc |= __shfl_xor_sync(0xffffffffu, acc, o);
            if ((t & 31) == 0) atomicOr(&sh_next[set], acc);
        }
        __syncthreads();
        if (lt == 0) sh_cur[set] = sh_next[set];
    }
    if (t == 0) { g_prog[b] = sh_chunks; g_comb[b] = sh_comb; }
}

__global__ void k_out(float* __restrict__ out, int B) {
    int b = blockIdx.x;
    int t = threadIdx.x;          // 128
    __shared__ int pref[NWORD];
    __shared__ u64 comb[NWORD];
    int chunks = g_prog[b];
    int nk = g_comb[b];
    if (nk > K_POST) nk = K_POST;
    float* outL = out + (size_t)b * K_POST * 5;
    float* outR = out + (size_t)(B + b) * K_POST * 5;
    for (int i = t; i < K_POST * 5; i += 128) {
        float v = (i % 5 == 0) ? (float)b : 0.f;
        outL[i] = v;
        outR[i] = v;
    }
    for (int w = t; w < NWORD; w += 128)
        comb[w] = (w < chunks) ? (g_keep[(b * 2) * NWORD + w] & g_keep[(b * 2 + 1) * NWORD + w]) : 0ull;
    __syncthreads();
    if (t == 0) {
        int s = 0;
        for (int w = 0; w < NWORD; w++) { pref[w] = s; s += __popcll(comb[w]); }
    }
    __syncthreads();
    for (int w = t; w < NWORD; w += 128) {
        int rank = pref[w];
        u64 m = comb[w];
        while (m && rank < nk) {
            int k = __ffsll((long long)m) - 1;
            m &= m - 1;
            int r = w * 64 + k;
            float4 bl = g_box[(b * 2 + 0) * NROW + r];
            float4 br = g_box[(b * 2 + 1) * NROW + r];
            outL[rank * 5 + 1] = bl.x; outL[rank * 5 + 2] = bl.y;
            outL[rank * 5 + 3] = bl.z; outL[rank * 5 + 4] = bl.w;
            outR[rank * 5 + 1] = br.x; outR[rank * 5 + 2] = br.y;
            outR[rank * 5 + 3] = br.z; outR[rank * 5 + 4] = br.w;
            rank++;
        }
    }
}

extern "C" void kernel_launch(void* const* d_in, const int* in_sizes, int n_in,
                              void* d_out, int out_size) {
    const float* scores  = (const float*)d_in[0];
    const float* deltas  = (const float*)d_in[1];
    const float* iminfo  = (const float*)d_in[2];
    const float* anchors = (const float*)d_in[3];
    float* out = (float*)d_out;
    int B = in_sizes[2] / 3;
    int N = in_sizes[3] / 4;
    int bn = B * N;
    int g = (bn + 255) / 256;

    k_zero<<<512, 256>>>(B);
    k_keys<<<g, 256>>>(scores, B, N);
    k_scan1<<<B, 256>>>();
    k_hist2<<<g, 256>>>(B, N);
    k_scan2<<<B, 32>>>();
    k_compact<<<g, 256>>>(B, N);
    k_rank<<<dim3(CAP / 128, B), 128>>>();
    k_gather<<<(B * NROW + 127) / 128, 128>>>(deltas, iminfo, anchors, B, N);
    k_mask<<<dim3(NWORD, NWORD, 2 * B), 64>>>();
    k_nms_scan<<<B, 128>>>();
    k_out<<<B, 128>>>(out, B);
}

// round 3
// speedup vs baseline: 1.1588x; 1.1588x over previous
#include <cuda_runtime.h>
#include <cstdint>
#include <math.h>

typedef unsigned long long u64;
typedef unsigned int u32;

#define K_PRE 6000
#define K_POST 300
#define NMS_TH 0.7f
#define NROW 6016
#define NWORD 94
#define WSTRIDE 96
#define MAXB 2
#define CAP 16384
#define SPEC_W 32          // speculative mask: first 32 column-words (2048 boxes)
#define SPEC_RT 8          // speculative mask: 8 row-tiles of 256 rows

// ---------- persistent device scratch (self-cleaning across graph replays) ----------
__device__ int    g_hist[MAXB * 65536];     // zeroed by k_thresh after reading
__device__ u32    g_T16[MAXB];
__device__ int    g_ccount[MAXB];           // zeroed by k_out
__device__ u64    g_cand[MAXB * CAP];
__device__ float4 g_box[2 * MAXB * NROW];
__device__ float  g_area[2 * MAXB * NROW];
__device__ u64    g_mask[(size_t)2 * MAXB * NROW * WSTRIDE];
__device__ u64    g_keep[2 * MAXB * NWORD];
__device__ int    g_prog[MAXB];
__device__ int    g_comb[MAXB];
__device__ int    g_full;                   // fallback flag, reset by k_out

// ---------- score -> monotone u32 ----------
__device__ __forceinline__ u32 score_map(float s) {
    u32 u = __float_as_uint(s);
    return (u & 0x80000000u) ? ~u : (u | 0x80000000u);
}

// ---------- 1: histogram of 16-bit score prefixes ----------
__global__ void k_hist(const float* __restrict__ scores, int B, int N) {
    int idx = blockIdx.x * blockDim.x + threadIdx.x;
    if (idx >= B * N) return;
    int b = idx / N;
    u32 u = score_map(scores[(size_t)idx * 2 + 1]);
    atomicAdd(&g_hist[(b << 16) + (int)(u >> 16)], 1);
}

// ---------- 2: find 16-bit threshold bin; re-zero histogram ----------
__global__ void k_thresh(void) {
    int b = blockIdx.x;
    int t = threadIdx.x;                  // 256
    __shared__ int part[256];
    int* h = &g_hist[b << 16];
    int sum = 0;
    for (int k = 0; k < 256; k++) sum += h[t * 256 + k];
    part[t] = sum;
    __syncthreads();
    if (t == 0) {
        int cum = 0, seg = 255;
        for (; seg > 0; seg--) {
            if (cum + part[seg] >= K_PRE) break;
            cum += part[seg];
        }
        int bin = seg * 256 + 255;
        int lo = seg * 256;
        for (;; bin--) {
            int c = h[bin];
            if (cum + c >= K_PRE || bin == lo) break;
            cum += c;
        }
        g_T16[b] = (u32)bin;
    }
    __syncthreads();
    for (int k = 0; k < 256; k++) h[t * 256 + k] = 0;   // self-clean for next replay
}

// ---------- 3: compact candidates with prefix16 >= threshold ----------
__global__ void k_compact(const float* __restrict__ scores, int B, int N) {
    int idx = blockIdx.x * blockDim.x + threadIdx.x;
    if (idx >= B * N) return;
    int b = idx / N;
    int i = idx - b * N;
    u32 u = score_map(scores[(size_t)idx * 2 + 1]);
    if ((u >> 16) >= g_T16[b]) {
        int p = atomicAdd(&g_ccount[b], 1);
        if (p < CAP)
            g_cand[b * CAP + p] = ((u64)u << 32) | (u32)(0xFFFFFFFFu - (u32)i);
    }
}

// ---------- 4: exact rank + box decode/clip (fused) ----------
__global__ void k_rank_gather(const float* __restrict__ deltas, const float* __restrict__ iminfo,
                              const float* __restrict__ anchors, int B, int N) {
    int b = blockIdx.y;
    int C = g_ccount[b];
    if (C > CAP) C = CAP;
    if ((int)blockIdx.x * 256 >= C) return;            // uniform per block
    int j = blockIdx.x * 256 + threadIdx.x;
    __shared__ u64 tile[1024];
    u64 mykey = (j < C) ? g_cand[b * CAP + j] : 0ull;
    int rank = 0;
    for (int base = 0; base < C; base += 1024) {
        int nt = min(1024, C - base);
        for (int t = threadIdx.x; t < nt; t += 256) tile[t] = g_cand[b * CAP + base + t];
        __syncthreads();
        if (j < C)
            for (int t = 0; t < nt; t++) rank += (tile[t] > mykey) ? 1 : 0;
        __syncthreads();
    }
    if (j >= C || rank >= K_PRE) return;
    int i = (int)(0xFFFFFFFFu - (u32)(mykey & 0xFFFFFFFFull));

    const float* a = anchors + (size_t)i * 4;
    float w = a[2] - a[0] + 1.0f;
    float h = a[3] - a[1] + 1.0f;
    float cx = a[0] + 0.5f * w;
    float cy = a[1] + 0.5f * h;
    const float* d = deltas + ((size_t)b * N + i) * 6;
    float d0 = d[0], d1 = d[1], d2 = d[2], d3 = d[3], d4 = d[4], d5 = d[5];
    float Hm1 = iminfo[b * 3 + 0] - 1.0f;
    float Wm1 = iminfo[b * 3 + 1] - 1.0f;
    float eh = (float)exp((double)d3) * h;   // accurate exp (fast-math safe)
    float pcy = d1 * h + cy;
    float y1 = fminf(fmaxf(pcy - 0.5f * eh, 0.f), Hm1);
    float y2 = fminf(fmaxf(pcy + 0.5f * eh, 0.f), Hm1);
    {
        float pcx = d0 * w + cx;
        float pw = (float)exp((double)d2) * w;
        float x1 = fminf(fmaxf(pcx - 0.5f * pw, 0.f), Wm1);
        float x2 = fminf(fmaxf(pcx + 0.5f * pw, 0.f), Wm1);
        g_box[(b * 2 + 0) * NROW + rank] = make_float4(x1, y1, x2, y2);
        g_area[(b * 2 + 0) * NROW + rank] = (x2 - x1 + 1.0f) * (y2 - y1 + 1.0f);
    }
    {
        float pcx = d4 * w + cx;
        float pw = (float)exp((double)d5) * w;
        float x1 = fminf(fmaxf(pcx - 0.5f * pw, 0.f), Wm1);
        float x2 = fminf(fmaxf(pcx + 0.5f * pw, 0.f), Wm1);
        g_box[(b * 2 + 1) * NROW + rank] = make_float4(x1, y1, x2, y2);
        g_area[(b * 2 + 1) * NROW + rank] = (x2 - x1 + 1.0f) * (y2 - y1 + 1.0f);
    }
}

// ---------- IoU mask tile: 256 rows x 64 cols ----------
struct TileSh { float x1[64], y1[64], x2[64], y2[64], ar[64]; };

__device__ __forceinline__ void do_tile(TileSh* sh, int bset, int rt, int cc) {
    int t = threadIdx.x;         // 256
    int jg0 = cc * 64;
    if (t < 64) {
        float4 bj = g_box[bset * NROW + jg0 + t];
        sh->x1[t] = bj.x; sh->y1[t] = bj.y; sh->x2[t] = bj.z; sh->y2[t] = bj.w;
        sh->ar[t] = g_area[bset * NROW + jg0 + t];
    }
    __syncthreads();
    int i = rt * 256 + t;
    if (i < NROW) {
        float4 bi = g_box[bset * NROW + i];
        float ai = g_area[bset * NROW + i];
        u64 word = 0;
#pragma unroll 4
        for (int k = 0; k < 64; k++) {
            float xx1 = fmaxf(bi.x, sh->x1[k]);
            float yy1 = fmaxf(bi.y, sh->y1[k]);
            float xx2 = fminf(bi.z, sh->x2[k]);
            float yy2 = fminf(bi.w, sh->y2[k]);
            float ow = xx2 - xx1 + 1.0f;
            float oh = yy2 - yy1 + 1.0f;
            bool sup = false;
            if (ow > 0.0f && oh > 0.0f && (jg0 + k) > i) {
                float inter = ow * oh;
                float uni = ai + sh->ar[k] - inter;
                float p = NMS_TH * uni;
                sup = inter > p;
                if (fabsf(inter - p) <= 1e-5f * uni)            // borderline: exact IEEE decision
                    sup = __fdiv_rn(inter, uni) > NMS_TH;
            }
            if (sup) word |= 1ull << k;
        }
        g_mask[((size_t)bset * NROW + i) * WSTRIDE + cc] = word;
    }
    __syncthreads();
}

// ---------- 5: speculative mask (first 2048 rows/cols) ----------
__global__ void k_mask_spec(void) {
    __shared__ TileSh sh;
    int cc = blockIdx.x;      // 0..SPEC_W-1
    int rt = blockIdx.y;      // 0..SPEC_RT-1
    if (cc < rt * 4) return;  // tile entirely below diagonal
    do_tile(&sh, blockIdx.z, rt, cc);
}

// ---------- 7: fallback full mask (persistent, flag-guarded, skips spec region) ----------
__global__ void k_mask_full(int B) {
    if (!g_full) return;
    __shared__ TileSh sh;
    const int PER_SET = 1008;            // tiles per set outside spec region
    int total = PER_SET * 2 * B;
    for (int tix = blockIdx.x; tix < total; tix += gridDim.x) {
        int set = tix / PER_SET;
        int r = tix - set * PER_SET;
        int rt, cc;
        if (r < 496) {                   // rt<8 : cc in [32,93]  -> 62 each
            rt = r / 62;
            cc = 32 + (r - rt * 62);
        } else {                         // rt>=8: cc in [4rt,93] -> 94-4rt each
            r -= 496;
            rt = 8;
            int cnt = 94 - 4 * 8;
            while (r >= cnt) { r -= cnt; rt++; cnt = 94 - 4 * rt; }
            cc = 4 * rt + r;
        }
        do_tile(&sh, set, rt, cc);
    }
}

// ---------- greedy NMS scan (shared by spec/full) ----------
__device__ __forceinline__ void scan_body(int b, int limit, int spec) {
    __shared__ u64 sh_keep[2][NWORD];
    __shared__ u64 sh_diag[2][64];
    __shared__ u64 sh_next[2], sh_cur[2];
    __shared__ int sh_comb, sh_done;
    int t = threadIdx.x;          // 128
    int set = t >> 6;
    int lt = t & 63;
    const u64* M = &g_mask[(size_t)(b * 2 + set) * NROW * WSTRIDE];
    if (t == 0) { sh_comb = 0; sh_done = 0; sh_cur[0] = 0; sh_cur[1] = 0; }
    __syncthreads();
    int c = 0;
    for (; c < limit; c++) {
        if (t < 2) sh_next[t] = 0;
        sh_diag[set][lt] = M[(size_t)(c * 64 + lt) * WSTRIDE + c];
        __syncthreads();
        if (lt == 0) {
            u64 cur = sh_cur[set];
            u64 keep = 0;
            int lim = min(64, K_PRE - c * 64);
            for (int k = 0; k < lim; k++) {
                if (!((cur >> k) & 1ull)) { keep |= 1ull << k; cur |= sh_diag[set][k]; }
            }
            sh_keep[set][c] = keep;
            g_keep[(b * 2 + set) * NWORD + c] = keep;
        }
        __syncthreads();
        if (t == 0) {
            sh_comb += __popcll(sh_keep[0][c] & sh_keep[1][c]);
            if (sh_comb >= K_POST) sh_done = 1;
        }
        __syncthreads();
        if (sh_done) { c++; break; }
        if (c + 1 < limit) {
            u64 acc = 0;
            for (int r = lt; r < (c + 1) * 64; r += 64) {
                u64 kw = sh_keep[set][r >> 6];
                if ((kw >> (r & 63)) & 1ull) acc |= M[(size_t)r * WSTRIDE + (c + 1)];
            }
            for (int o = 16; o; o >>= 1) acc |= __shfl_xor_sync(0xffffffffu, acc, o);
            if ((t & 31) == 0) atomicOr(&sh_next[set], acc);
            __syncthreads();
            if (lt == 0) sh_cur[set] = sh_next[set];
        }
    }
    if (t == 0) {
        if (spec && !sh_done) {
            g_full = 1;                       // fallback path takes over
        } else {
            g_prog[b] = c;
            g_comb[b] = sh_comb;
        }
    }
}

__global__ void k_scan_spec(void) { scan_body(blockIdx.x, SPEC_W, 1); }
__global__ void k_scan_full(void) { if (g_full) scan_body(blockIdx.x, NWORD, 0); }

// ---------- 9: emit outputs + self-clean counters ----------
__global__ void k_out(float* __restrict__ out, int B) {
    int b = blockIdx.x;
    int t = threadIdx.x;          // 128
    __shared__ int pref[NWORD];
    __shared__ u64 comb[NWORD];
    int chunks = g_prog[b];
    int nk = g_comb[b];
    if (nk > K_POST) nk = K_POST;
    float* outL = out + (size_t)b * K_POST * 5;
    float* outR = out + (size_t)(B + b) * K_POST * 5;
    for (int i = t; i < K_POST * 5; i += 128) {
        float v = (i % 5 == 0) ? (float)b : 0.f;
        outL[i] = v;
        outR[i] = v;
    }
    for (int w = t; w < NWORD; w += 128)
        comb[w] = (w < chunks) ? (g_keep[(b * 2) * NWORD + w] & g_keep[(b * 2 + 1) * NWORD + w]) : 0ull;
    __syncthreads();
    if (t == 0) {
        int s = 0;
        for (int w = 0; w < NWORD; w++) { pref[w] = s; s += __popcll(comb[w]); }
        g_ccount[b] = 0;                      // self-clean for next replay
        if (b == 0) g_full = 0;
    }
    __syncthreads();
    for (int w = t; w < NWORD; w += 128) {
        int rank = pref[w];
        u64 m = comb[w];
        while (m && rank < nk) {
            int k = __ffsll((long long)m) - 1;
            m &= m - 1;
            int r = w * 64 + k;
            float4 bl = g_box[(b * 2 + 0) * NROW + r];
            float4 br = g_box[(b * 2 + 1) * NROW + r];
            outL[rank * 5 + 1] = bl.x; outL[rank * 5 + 2] = bl.y;
            outL[rank * 5 + 3] = bl.z; outL[rank * 5 + 4] = bl.w;
            outR[rank * 5 + 1] = br.x; outR[rank * 5 + 2] = br.y;
            outR[rank * 5 + 3] = br.z; outR[rank * 5 + 4] = br.w;
            rank++;
        }
    }
}

extern "C" void kernel_launch(void* const* d_in, const int* in_sizes, int n_in,
                              void* d_out, int out_size) {
    const float* scores  = (const float*)d_in[0];
    const float* deltas  = (const float*)d_in[1];
    const float* iminfo  = (const float*)d_in[2];
    const float* anchors = (const float*)d_in[3];
    float* out = (float*)d_out;
    int B = in_sizes[2] / 3;
    int N = in_sizes[3] / 4;
    int bn = B * N;
    int g = (bn + 255) / 256;

    k_hist<<<g, 256>>>(scores, B, N);
    k_thresh<<<B, 256>>>();
    k_compact<<<g, 256>>>(scores, B, N);
    k_rank_gather<<<dim3(CAP / 256, B), 256>>>(deltas, iminfo, anchors, B, N);
    k_mask_spec<<<dim3(SPEC_W, SPEC_RT, 2 * B), 256>>>();
    k_scan_spec<<<B, 128>>>();
    k_mask_full<<<296, 256>>>(B);     // no-op unless g_full set
    k_scan_full<<<B, 128>>>();        // no-op unless g_full set
    k_out<<<B, 128>>>(out, B);
}

// round 4
// speedup vs baseline: 1.3333x; 1.1506x over previous
#include <cuda_runtime.h>
#include <cstdint>
#include <math.h>

typedef unsigned long long u64;
typedef unsigned int u32;

#define K_PRE 6000
#define K_POST 300
#define NMS_TH 0.7f
#define NROW 6016
#define NWORD 94
#define WSTRIDE 96
#define MAXB 2
#define CAP 16384
#define SPEC_W 32          // speculative mask: first 32 column-words (2048 boxes)
#define SPEC_RT 8          // speculative mask: 8 row-tiles of 256 rows

// ---------- persistent device scratch (self-cleaning across graph replays) ----------
__device__ int    g_hist[MAXB * 65536];     // zeroed by k_thresh after reading
__device__ u32    g_T16[MAXB];
__device__ int    g_ccount[MAXB];           // zeroed by k_out
__device__ u64    g_cand[MAXB * CAP];
__device__ int    g_rank[MAXB * CAP];       // zeroed by k_thresh
__device__ float4 g_box[2 * MAXB * NROW];
__device__ float  g_area[2 * MAXB * NROW];
__device__ u64    g_mask[(size_t)2 * MAXB * NROW * WSTRIDE];
__device__ u64    g_keep[2 * MAXB * NWORD];
__device__ int    g_prog[MAXB];
__device__ int    g_comb[MAXB];
__device__ int    g_full;                   // fallback flag, reset by k_out

// ---------- score -> monotone u32 ----------
__device__ __forceinline__ u32 score_map(float s) {
    u32 u = __float_as_uint(s);
    return (u & 0x80000000u) ? ~u : (u | 0x80000000u);
}

// ---------- 1: histogram of 16-bit score prefixes ----------
__global__ void k_hist(const float* __restrict__ scores, int B, int N) {
    int idx = blockIdx.x * blockDim.x + threadIdx.x;
    if (idx >= B * N) return;
    int b = idx / N;
    u32 u = score_map(scores[(size_t)idx * 2 + 1]);
    atomicAdd(&g_hist[(b << 16) + (int)(u >> 16)], 1);
}

// ---------- 2: find 16-bit threshold bin; re-zero histogram + rank buffer ----------
__global__ void k_thresh(void) {
    int b = blockIdx.x;
    int t = threadIdx.x;                  // 256
    __shared__ int part[256];
    int* h = &g_hist[b << 16];
    int sum = 0;
    for (int k = 0; k < 256; k++) sum += h[t * 256 + k];
    part[t] = sum;
    __syncthreads();
    if (t == 0) {
        int cum = 0, seg = 255;
        for (; seg > 0; seg--) {
            if (cum + part[seg] >= K_PRE) break;
            cum += part[seg];
        }
        int bin = seg * 256 + 255;
        int lo = seg * 256;
        for (;; bin--) {
            int c = h[bin];
            if (cum + c >= K_PRE || bin == lo) break;
            cum += c;
        }
        g_T16[b] = (u32)bin;
    }
    __syncthreads();
    for (int k = 0; k < 256; k++) h[t * 256 + k] = 0;     // self-clean for next replay
    for (int k = t; k < CAP; k += 256) g_rank[b * CAP + k] = 0;
}

// ---------- 3: compact candidates with prefix16 >= threshold ----------
__global__ void k_compact(const float* __restrict__ scores, int B, int N) {
    int idx = blockIdx.x * blockDim.x + threadIdx.x;
    if (idx >= B * N) return;
    int b = idx / N;
    int i = idx - b * N;
    u32 u = score_map(scores[(size_t)idx * 2 + 1]);
    if ((u >> 16) >= g_T16[b]) {
        int p = atomicAdd(&g_ccount[b], 1);
        if (p < CAP)
            g_cand[b * CAP + p] = ((u64)u << 32) | (u32)(0xFFFFFFFFu - (u32)i);
    }
}

// ---------- 4: parallel partial rank counting (atomic accumulate) ----------
#define RC_COLS 2048
__global__ void k_rankcnt(void) {
    int b = blockIdx.z;
    int C = g_ccount[b];
    if (C > CAP) C = CAP;
    int j0 = blockIdx.x * 256;
    int c0 = blockIdx.y * RC_COLS;
    if (j0 >= C || c0 >= C) return;        // uniform per block
    __shared__ u64 tile[RC_COLS];
    int j = j0 + threadIdx.x;
    u64 my = (j < C) ? g_cand[b * CAP + j] : ~0ull;
    int nt = min(RC_COLS, C - c0);
    for (int t = threadIdx.x; t < nt; t += 256) tile[t] = g_cand[b * CAP + c0 + t];
    __syncthreads();
    int r = 0;
#pragma unroll 8
    for (int t = 0; t < nt; t++) r += (tile[t] > my) ? 1 : 0;
    if (j < C && r) atomicAdd(&g_rank[b * CAP + j], r);
}

// ---------- 5: gather + decode + clip by final rank ----------
__global__ void k_gather(const float* __restrict__ deltas, const float* __restrict__ iminfo,
                         const float* __restrict__ anchors, int B, int N) {
    int b = blockIdx.y;
    int C = g_ccount[b];
    if (C > CAP) C = CAP;
    if ((int)blockIdx.x * 256 >= C) return;
    int j = blockIdx.x * 256 + threadIdx.x;
    if (j >= C) return;
    int rank = g_rank[b * CAP + j];
    if (rank >= K_PRE) return;
    u64 mykey = g_cand[b * CAP + j];
    int i = (int)(0xFFFFFFFFu - (u32)(mykey & 0xFFFFFFFFull));

    const float* a = anchors + (size_t)i * 4;
    float w = a[2] - a[0] + 1.0f;
    float h = a[3] - a[1] + 1.0f;
    float cx = a[0] + 0.5f * w;
    float cy = a[1] + 0.5f * h;
    const float* d = deltas + ((size_t)b * N + i) * 6;
    float d0 = d[0], d1 = d[1], d2 = d[2], d3 = d[3], d4 = d[4], d5 = d[5];
    float Hm1 = iminfo[b * 3 + 0] - 1.0f;
    float Wm1 = iminfo[b * 3 + 1] - 1.0f;
    float eh = (float)exp((double)d3) * h;   // accurate exp (fast-math safe)
    float pcy = d1 * h + cy;
    float y1 = fminf(fmaxf(pcy - 0.5f * eh, 0.f), Hm1);
    float y2 = fminf(fmaxf(pcy + 0.5f * eh, 0.f), Hm1);
    {
        float pcx = d0 * w + cx;
        float pw = (float)exp((double)d2) * w;
        float x1 = fminf(fmaxf(pcx - 0.5f * pw, 0.f), Wm1);
        float x2 = fminf(fmaxf(pcx + 0.5f * pw, 0.f), Wm1);
        g_box[(b * 2 + 0) * NROW + rank] = make_float4(x1, y1, x2, y2);
        g_area[(b * 2 + 0) * NROW + rank] = (x2 - x1 + 1.0f) * (y2 - y1 + 1.0f);
    }
    {
        float pcx = d4 * w + cx;
        float pw = (float)exp((double)d5) * w;
        float x1 = fminf(fmaxf(pcx - 0.5f * pw, 0.f), Wm1);
        float x2 = fminf(fmaxf(pcx + 0.5f * pw, 0.f), Wm1);
        g_box[(b * 2 + 1) * NROW + rank] = make_float4(x1, y1, x2, y2);
        g_area[(b * 2 + 1) * NROW + rank] = (x2 - x1 + 1.0f) * (y2 - y1 + 1.0f);
    }
}

// ---------- IoU mask tile: 256 rows x 64 cols ----------
struct TileSh { float x1[64], y1[64], x2[64], y2[64], ar[64]; };

__device__ __forceinline__ void do_tile(TileSh* sh, int bset, int rt, int cc) {
    int t = threadIdx.x;         // 256
    int jg0 = cc * 64;
    if (t < 64) {
        float4 bj = g_box[bset * NROW + jg0 + t];
        sh->x1[t] = bj.x; sh->y1[t] = bj.y; sh->x2[t] = bj.z; sh->y2[t] = bj.w;
        sh->ar[t] = g_area[bset * NROW + jg0 + t];
    }
    __syncthreads();
    int i = rt * 256 + t;
    if (i < NROW) {
        float4 bi = g_box[bset * NROW + i];
        float ai = g_area[bset * NROW + i];
        u64 word = 0;
#pragma unroll 4
        for (int k = 0; k < 64; k++) {
            float xx1 = fmaxf(bi.x, sh->x1[k]);
            float yy1 = fmaxf(bi.y, sh->y1[k]);
            float xx2 = fminf(bi.z, sh->x2[k]);
            float yy2 = fminf(bi.w, sh->y2[k]);
            float ow = xx2 - xx1 + 1.0f;
            float oh = yy2 - yy1 + 1.0f;
            bool sup = false;
            if (ow > 0.0f && oh > 0.0f && (jg0 + k) > i) {
                float inter = ow * oh;
                float uni = ai + sh->ar[k] - inter;
                float p = NMS_TH * uni;
                sup = inter > p;
                if (fabsf(inter - p) <= 1e-5f * uni)            // borderline: exact IEEE decision
                    sup = __fdiv_rn(inter, uni) > NMS_TH;
            }
            if (sup) word |= 1ull << k;
        }
        g_mask[((size_t)bset * NROW + i) * WSTRIDE + cc] = word;
    }
    __syncthreads();
}

// ---------- 6: speculative mask (first 2048 rows/cols) ----------
__global__ void k_mask_spec(void) {
    __shared__ TileSh sh;
    int cc = blockIdx.x;      // 0..SPEC_W-1
    int rt = blockIdx.y;      // 0..SPEC_RT-1
    if (cc < rt * 4) return;  // tile entirely below diagonal
    do_tile(&sh, blockIdx.z, rt, cc);
}

// ---------- 8: fallback full mask (flag-guarded, skips spec region) ----------
__global__ void k_mask_full(int B) {
    if (!g_full) return;
    __shared__ TileSh sh;
    const int PER_SET = 1008;            // tiles per set outside spec region
    int total = PER_SET * 2 * B;
    for (int tix = blockIdx.x; tix < total; tix += gridDim.x) {
        int set = tix / PER_SET;
        int r = tix - set * PER_SET;
        int rt, cc;
        if (r < 496) {                   // rt<8 : cc in [32,93]  -> 62 each
            rt = r / 62;
            cc = 32 + (r - rt * 62);
        } else {                         // rt>=8: cc in [4rt,93] -> 94-4rt each
            r -= 496;
            rt = 8;
            int cnt = 94 - 4 * 8;
            while (r >= cnt) { r -= cnt; rt++; cnt = 94 - 4 * rt; }
            cc = 4 * rt + r;
        }
        do_tile(&sh, set, rt, cc);
    }
}

// ---------- greedy NMS scan (shared by spec/full) ----------
__device__ __forceinline__ void scan_body(int b, int limit, int spec) {
    __shared__ u64 sh_keep[2][NWORD];
    __shared__ u64 sh_diag[2][64];
    __shared__ u64 sh_next[2], sh_cur[2];
    __shared__ int sh_comb, sh_done;
    int t = threadIdx.x;          // 128
    int set = t >> 6;
    int lt = t & 63;
    const u64* M = &g_mask[(size_t)(b * 2 + set) * NROW * WSTRIDE];
    if (t == 0) { sh_comb = 0; sh_done = 0; sh_cur[0] = 0; sh_cur[1] = 0; }
    __syncthreads();
    int c = 0;
    for (; c < limit; c++) {
        if (t < 2) sh_next[t] = 0;
        sh_diag[set][lt] = M[(size_t)(c * 64 + lt) * WSTRIDE + c];
        __syncthreads();
        if (lt == 0) {
            u64 cur = sh_cur[set];
            u64 keep = 0;
            int lim = min(64, K_PRE - c * 64);
            for (int k = 0; k < lim; k++) {
                if (!((cur >> k) & 1ull)) { keep |= 1ull << k; cur |= sh_diag[set][k]; }
            }
            sh_keep[set][c] = keep;
            g_keep[(b * 2 + set) * NWORD + c] = keep;
        }
        __syncthreads();
        if (t == 0) {
            sh_comb += __popcll(sh_keep[0][c] & sh_keep[1][c]);
            if (sh_comb >= K_POST) sh_done = 1;
        }
        __syncthreads();
        if (sh_done) { c++; break; }
        if (c + 1 < limit) {
            u64 acc = 0;
            for (int r = lt; r < (c + 1) * 64; r += 64) {
                u64 kw = sh_keep[set][r >> 6];
                if ((kw >> (r & 63)) & 1ull) acc |= M[(size_t)r * WSTRIDE + (c + 1)];
            }
            for (int o = 16; o; o >>= 1) acc |= __shfl_xor_sync(0xffffffffu, acc, o);
            if ((t & 31) == 0) atomicOr(&sh_next[set], acc);
            __syncthreads();
            if (lt == 0) sh_cur[set] = sh_next[set];
        }
    }
    if (t == 0) {
        if (spec && !sh_done) {
            g_full = 1;                       // fallback path takes over
        } else {
            g_prog[b] = c;
            g_comb[b] = sh_comb;
        }
    }
}

__global__ void k_scan_spec(void) { scan_body(blockIdx.x, SPEC_W, 1); }
__global__ void k_scan_full(void) { if (g_full) scan_body(blockIdx.x, NWORD, 0); }

// ---------- 10: emit outputs + self-clean counters ----------
__global__ void k_out(float* __restrict__ out, int B) {
    int b = blockIdx.x;
    int t = threadIdx.x;          // 128
    __shared__ int pref[NWORD];
    __shared__ u64 comb[NWORD];
    int chunks = g_prog[b];
    int nk = g_comb[b];
    if (nk > K_POST) nk = K_POST;
    float* outL = out + (size_t)b * K_POST * 5;
    float* outR = out + (size_t)(B + b) * K_POST * 5;
    for (int i = t; i < K_POST * 5; i += 128) {
        float v = (i % 5 == 0) ? (float)b : 0.f;
        outL[i] = v;
        outR[i] = v;
    }
    for (int w = t; w < NWORD; w += 128)
        comb[w] = (w < chunks) ? (g_keep[(b * 2) * NWORD + w] & g_keep[(b * 2 + 1) * NWORD + w]) : 0ull;
    __syncthreads();
    if (t == 0) {
        int s = 0;
        for (int w = 0; w < NWORD; w++) { pref[w] = s; s += __popcll(comb[w]); }
        g_ccount[b] = 0;                      // self-clean for next replay
        if (b == 0) g_full = 0;
    }
    __syncthreads();
    for (int w = t; w < NWORD; w += 128) {
        int rank = pref[w];
        u64 m = comb[w];
        while (m && rank < nk) {
            int k = __ffsll((long long)m) - 1;
            m &= m - 1;
            int r = w * 64 + k;
            float4 bl = g_box[(b * 2 + 0) * NROW + r];
            float4 br = g_box[(b * 2 + 1) * NROW + r];
            outL[rank * 5 + 1] = bl.x; outL[rank * 5 + 2] = bl.y;
            outL[rank * 5 + 3] = bl.z; outL[rank * 5 + 4] = bl.w;
            outR[rank * 5 + 1] = br.x; outR[rank * 5 + 2] = br.y;
            outR[rank * 5 + 3] = br.z; outR[rank * 5 + 4] = br.w;
            rank++;
        }
    }
}

extern "C" void kernel_launch(void* const* d_in, const int* in_sizes, int n_in,
                              void* d_out, int out_size) {
    const float* scores  = (const float*)d_in[0];
    const float* deltas  = (const float*)d_in[1];
    const float* iminfo  = (const float*)d_in[2];
    const float* anchors = (const float*)d_in[3];
    float* out = (float*)d_out;
    int B = in_sizes[2] / 3;
    int N = in_sizes[3] / 4;
    int bn = B * N;
    int g = (bn + 255) / 256;

    k_hist<<<g, 256>>>(scores, B, N);
    k_thresh<<<B, 256>>>();
    k_compact<<<g, 256>>>(scores, B, N);
    k_rankcnt<<<dim3(CAP / 256, CAP / RC_COLS, B), 256>>>();
    k_gather<<<dim3(CAP / 256, B), 256>>>(deltas, iminfo, anchors, B, N);
    k_mask_spec<<<dim3(SPEC_W, SPEC_RT, 2 * B), 256>>>();
    k_scan_spec<<<B, 128>>>();
    k_mask_full<<<296, 256>>>(B);     // no-op unless g_full set
    k_scan_full<<<B, 128>>>();        // no-op unless g_full set
    k_out<<<B, 128>>>(out, B);
}